// round 1
// baseline (speedup 1.0000x reference)
#include <cuda_runtime.h>
#include <cstdint>

// Problem constants
constexpr int NB = 8;      // batch
constexpr int T  = 1024;   // sequence
constexpr int D  = 512;    // model dim
constexpr int H  = 8;      // heads
constexpr int HD = 64;     // head dim
constexpr int M  = NB * T; // 8192 rows

// ---------------- scratch (device globals; allocation-free at runtime) -------
__device__ float g_xn[M * D];          // layernorm output
__device__ float g_qu[M * D];          // Q + bq + u
__device__ float g_qv[M * D];          // Q + bq + v
__device__ float g_k [M * D];
__device__ float g_v [M * D];
__device__ float g_p [M * D];
__device__ float g_ctx[M * D];
__device__ float g_scores[(size_t)NB * H * T * T]; // content scores -> attn (in place)
__device__ float g_bd    [(size_t)NB * H * T * T]; // positional scores (pre-shift)

// ---------------- LayerNorm --------------------------------------------------
__global__ void ln_kernel(const float* __restrict__ x,
                          const float* __restrict__ gamma,
                          const float* __restrict__ beta,
                          float* __restrict__ out) {
    int row = blockIdx.x;
    int t = threadIdx.x; // 128 threads, 128 float4 per row
    const float4* xr = reinterpret_cast<const float4*>(x + (size_t)row * D);
    float4 v = xr[t];
    float s = v.x + v.y + v.z + v.w;
    __shared__ float red[4], red2[4];
    #pragma unroll
    for (int o = 16; o > 0; o >>= 1) s += __shfl_xor_sync(0xffffffffu, s, o);
    if ((t & 31) == 0) red[t >> 5] = s;
    __syncthreads();
    float mu = (red[0] + red[1] + red[2] + red[3]) * (1.0f / D);
    float dx = v.x - mu, dy = v.y - mu, dz = v.z - mu, dw = v.w - mu;
    float ss = dx * dx + dy * dy + dz * dz + dw * dw;
    #pragma unroll
    for (int o = 16; o > 0; o >>= 1) ss += __shfl_xor_sync(0xffffffffu, ss, o);
    if ((t & 31) == 0) red2[t >> 5] = ss;
    __syncthreads();
    float var = (red2[0] + red2[1] + red2[2] + red2[3]) * (1.0f / D);
    float rstd = rsqrtf(var + 1e-3f);
    const float4* g4 = reinterpret_cast<const float4*>(gamma);
    const float4* b4 = reinterpret_cast<const float4*>(beta);
    float4 g = g4[t], b = b4[t];
    float4 o4;
    o4.x = dx * rstd * g.x + b.x;
    o4.y = dy * rstd * g.y + b.y;
    o4.z = dz * rstd * g.z + b.z;
    o4.w = dw * rstd * g.w + b.w;
    reinterpret_cast<float4*>(out + (size_t)row * D)[t] = o4;
}

// ---------------- generic SGEMM: C[M,512] = A[M,512] @ W[512,512] ------------
// out1 = acc + bias + biasU (+ resid) ; out2 = acc + bias + biasV (optional)
__global__ void sgemm512(const float* __restrict__ A, const float* __restrict__ W,
                         const float* __restrict__ bias, const float* __restrict__ biasU,
                         const float* __restrict__ resid, float* __restrict__ out1,
                         const float* __restrict__ biasV, float* __restrict__ out2) {
    __shared__ float As[16][64]; // As[k][m] (transposed)
    __shared__ float Ws[16][64]; // Ws[k][n]
    int t = threadIdx.x;            // 256 threads
    int bm = blockIdx.y * 64, bn = blockIdx.x * 64;
    int tx = t & 15, ty = t >> 4;
    int aRow = t >> 2, aC = (t & 3) * 4;
    int wRow = t >> 4, wC = (t & 15) * 4;
    const float* Aptr = A + (size_t)(bm + aRow) * D + aC;
    const float* Wptr = W + (size_t)wRow * D + bn + wC;
    float acc[4][4];
    #pragma unroll
    for (int i = 0; i < 4; i++)
        #pragma unroll
        for (int j = 0; j < 4; j++) acc[i][j] = 0.f;

    for (int k0 = 0; k0 < D; k0 += 16) {
        float4 av = *reinterpret_cast<const float4*>(Aptr + k0);
        float4 wv = *reinterpret_cast<const float4*>(Wptr + (size_t)k0 * D);
        __syncthreads();
        As[aC + 0][aRow] = av.x; As[aC + 1][aRow] = av.y;
        As[aC + 2][aRow] = av.z; As[aC + 3][aRow] = av.w;
        *reinterpret_cast<float4*>(&Ws[wRow][wC]) = wv;
        __syncthreads();
        #pragma unroll
        for (int kk = 0; kk < 16; kk++) {
            float a0 = As[kk][ty * 4 + 0], a1 = As[kk][ty * 4 + 1];
            float a2 = As[kk][ty * 4 + 2], a3 = As[kk][ty * 4 + 3];
            float w0 = Ws[kk][tx * 4 + 0], w1 = Ws[kk][tx * 4 + 1];
            float w2 = Ws[kk][tx * 4 + 2], w3 = Ws[kk][tx * 4 + 3];
            acc[0][0] += a0 * w0; acc[0][1] += a0 * w1; acc[0][2] += a0 * w2; acc[0][3] += a0 * w3;
            acc[1][0] += a1 * w0; acc[1][1] += a1 * w1; acc[1][2] += a1 * w2; acc[1][3] += a1 * w3;
            acc[2][0] += a2 * w0; acc[2][1] += a2 * w1; acc[2][2] += a2 * w2; acc[2][3] += a2 * w3;
            acc[3][0] += a3 * w0; acc[3][1] += a3 * w1; acc[3][2] += a3 * w2; acc[3][3] += a3 * w3;
        }
    }

    #pragma unroll
    for (int ii = 0; ii < 4; ii++) {
        int r = bm + ty * 4 + ii;
        #pragma unroll
        for (int jj = 0; jj < 4; jj++) {
            int c = bn + tx * 4 + jj;
            float base = acc[ii][jj];
            if (bias)  base += bias[c];
            float v1 = base;
            if (biasU) v1 += biasU[c];
            if (resid) v1 += resid[(size_t)r * D + c];
            out1[(size_t)r * D + c] = v1;
            if (out2) {
                float v2 = base + biasV[c];
                out2[(size_t)r * D + c] = v2;
            }
        }
    }
}

// ---------------- batched score GEMM: S[bh,i,j] = sum_c Q[i,c]*K[j,c] -------
__global__ void score_gemm(const float* __restrict__ Qx, const float* __restrict__ Kx,
                           float* __restrict__ S) {
    int bh = blockIdx.z;
    int b = bh >> 3, h = bh & 7;
    int i0 = blockIdx.y * 64, j0 = blockIdx.x * 64;
    const float* Qb = Qx + (size_t)b * T * D + h * HD;
    const float* Kb = Kx + (size_t)b * T * D + h * HD;
    __shared__ float As[64][68]; // As[c][i]
    __shared__ float Bs[64][68]; // Bs[c][j]
    int t = threadIdx.x; // 256
    int lr = t >> 4, lc = (t & 15) * 4;
    #pragma unroll
    for (int p = 0; p < 4; p++) {
        int r = lr + p * 16;
        float4 qa = *reinterpret_cast<const float4*>(Qb + (size_t)(i0 + r) * D + lc);
        float4 kb = *reinterpret_cast<const float4*>(Kb + (size_t)(j0 + r) * D + lc);
        As[lc + 0][r] = qa.x; As[lc + 1][r] = qa.y; As[lc + 2][r] = qa.z; As[lc + 3][r] = qa.w;
        Bs[lc + 0][r] = kb.x; Bs[lc + 1][r] = kb.y; Bs[lc + 2][r] = kb.z; Bs[lc + 3][r] = kb.w;
    }
    __syncthreads();
    int tx = t & 15, ty = t >> 4;
    float acc[4][4];
    #pragma unroll
    for (int i = 0; i < 4; i++)
        #pragma unroll
        for (int j = 0; j < 4; j++) acc[i][j] = 0.f;
    #pragma unroll 8
    for (int c = 0; c < 64; c++) {
        float4 a = *reinterpret_cast<const float4*>(&As[c][ty * 4]);
        float4 bq = *reinterpret_cast<const float4*>(&Bs[c][tx * 4]);
        acc[0][0] += a.x * bq.x; acc[0][1] += a.x * bq.y; acc[0][2] += a.x * bq.z; acc[0][3] += a.x * bq.w;
        acc[1][0] += a.y * bq.x; acc[1][1] += a.y * bq.y; acc[1][2] += a.y * bq.z; acc[1][3] += a.y * bq.w;
        acc[2][0] += a.z * bq.x; acc[2][1] += a.z * bq.y; acc[2][2] += a.z * bq.z; acc[2][3] += a.z * bq.w;
        acc[3][0] += a.w * bq.x; acc[3][1] += a.w * bq.y; acc[3][2] += a.w * bq.z; acc[3][3] += a.w * bq.w;
    }
    #pragma unroll
    for (int ii = 0; ii < 4; ii++) {
        size_t off = ((size_t)bh * T + (i0 + ty * 4 + ii)) * T + j0 + tx * 4;
        float4 o = make_float4(acc[ii][0], acc[ii][1], acc[ii][2], acc[ii][3]);
        *reinterpret_cast<float4*>(S + off) = o;
    }
}

// ---------------- shift + softmax (row-wise, in place on S) ------------------
__global__ void softmax_shift(float* __restrict__ S, const float* __restrict__ BD) {
    int i = blockIdx.x;
    int bh = blockIdx.y;
    size_t rowOff = ((size_t)bh * T + i) * T;
    float* srow = S + rowOff;
    const float* bdi  = BD + rowOff;
    const float* bdi1 = bdi + T; // only dereferenced when i+1 <= T-1
    int t = threadIdx.x; // 256
    float vals[4];
    float mx = -3.4e38f;
    #pragma unroll
    for (int q = 0; q < 4; q++) {
        int j = q * 256 + t;
        float sh;
        if (j <= i)           sh = bdi[T - 1 - i + j];
        else if (j == i + 1)  sh = 0.f;
        else                  sh = bdi1[j - i - 2];
        float val = (srow[j] + sh) * 0.125f; // 1/sqrt(64)
        vals[q] = val;
        mx = fmaxf(mx, val);
    }
    __shared__ float red[8], red2[8];
    #pragma unroll
    for (int o = 16; o > 0; o >>= 1) mx = fmaxf(mx, __shfl_xor_sync(0xffffffffu, mx, o));
    if ((t & 31) == 0) red[t >> 5] = mx;
    __syncthreads();
    mx = red[0];
    #pragma unroll
    for (int w = 1; w < 8; w++) mx = fmaxf(mx, red[w]);
    float sum = 0.f;
    #pragma unroll
    for (int q = 0; q < 4; q++) {
        vals[q] = expf(vals[q] - mx);
        sum += vals[q];
    }
    #pragma unroll
    for (int o = 16; o > 0; o >>= 1) sum += __shfl_xor_sync(0xffffffffu, sum, o);
    if ((t & 31) == 0) red2[t >> 5] = sum;
    __syncthreads();
    sum = red2[0] + red2[1] + red2[2] + red2[3] + red2[4] + red2[5] + red2[6] + red2[7];
    float inv = 1.0f / sum;
    #pragma unroll
    for (int q = 0; q < 4; q++) {
        int j = q * 256 + t;
        srow[j] = vals[q] * inv;
    }
}

// ---------------- attn @ V ---------------------------------------------------
__global__ void attn_v(const float* __restrict__ S, const float* __restrict__ V,
                       float* __restrict__ ctx) {
    int bh = blockIdx.y;
    int b = bh >> 3, h = bh & 7;
    int i0 = blockIdx.x * 64;
    const float* Sb = S + ((size_t)bh * T + i0) * T;
    const float* Vb = V + (size_t)b * T * D + h * HD;
    float* Cb = ctx + ((size_t)(b * T) + i0) * D + h * HD;
    __shared__ float As[32][68]; // As[k][i] (transposed attn tile)
    __shared__ float Vs[32][64]; // Vs[k][f]
    int t = threadIdx.x;
    int tx = t & 15, ty = t >> 4;
    float acc[4][4];
    #pragma unroll
    for (int i = 0; i < 4; i++)
        #pragma unroll
        for (int j = 0; j < 4; j++) acc[i][j] = 0.f;

    int ar = t >> 3, ac = (t & 7) * 4;   // attn tile: 64 rows x 32 cols
    int vr = t >> 4, vc = (t & 15) * 4;  // V tile: 32 rows x 64 cols

    for (int k0 = 0; k0 < T; k0 += 32) {
        float4 a0 = *reinterpret_cast<const float4*>(Sb + (size_t)ar * T + k0 + ac);
        float4 a1 = *reinterpret_cast<const float4*>(Sb + (size_t)(ar + 32) * T + k0 + ac);
        float4 v0 = *reinterpret_cast<const float4*>(Vb + (size_t)(k0 + vr) * D + vc);
        float4 v1 = *reinterpret_cast<const float4*>(Vb + (size_t)(k0 + vr + 16) * D + vc);
        __syncthreads();
        As[ac + 0][ar] = a0.x; As[ac + 1][ar] = a0.y; As[ac + 2][ar] = a0.z; As[ac + 3][ar] = a0.w;
        As[ac + 0][ar + 32] = a1.x; As[ac + 1][ar + 32] = a1.y; As[ac + 2][ar + 32] = a1.z; As[ac + 3][ar + 32] = a1.w;
        *reinterpret_cast<float4*>(&Vs[vr][vc]) = v0;
        *reinterpret_cast<float4*>(&Vs[vr + 16][vc]) = v1;
        __syncthreads();
        #pragma unroll
        for (int kk = 0; kk < 32; kk++) {
            float4 a = *reinterpret_cast<const float4*>(&As[kk][ty * 4]);
            float4 v = *reinterpret_cast<const float4*>(&Vs[kk][tx * 4]);
            acc[0][0] += a.x * v.x; acc[0][1] += a.x * v.y; acc[0][2] += a.x * v.z; acc[0][3] += a.x * v.w;
            acc[1][0] += a.y * v.x; acc[1][1] += a.y * v.y; acc[1][2] += a.y * v.z; acc[1][3] += a.y * v.w;
            acc[2][0] += a.z * v.x; acc[2][1] += a.z * v.y; acc[2][2] += a.z * v.z; acc[2][3] += a.z * v.w;
            acc[3][0] += a.w * v.x; acc[3][1] += a.w * v.y; acc[3][2] += a.w * v.z; acc[3][3] += a.w * v.w;
        }
    }
    #pragma unroll
    for (int ii = 0; ii < 4; ii++) {
        float4 o = make_float4(acc[ii][0], acc[ii][1], acc[ii][2], acc[ii][3]);
        *reinterpret_cast<float4*>(Cb + (size_t)(ty * 4 + ii) * D + tx * 4) = o;
    }
}

// ---------------- launch -----------------------------------------------------
extern "C" void kernel_launch(void* const* d_in, const int* in_sizes, int n_in,
                              void* d_out, int out_size) {
    const float* inputs = (const float*)d_in[0];
    const float* pos    = (const float*)d_in[1];
    const float* gamma  = (const float*)d_in[2];
    const float* beta   = (const float*)d_in[3];
    const float* wq     = (const float*)d_in[4];
    const float* bq     = (const float*)d_in[5];
    const float* wk     = (const float*)d_in[6];
    const float* bk     = (const float*)d_in[7];
    const float* wv     = (const float*)d_in[8];
    const float* bv     = (const float*)d_in[9];
    const float* wpos   = (const float*)d_in[10];
    const float* u      = (const float*)d_in[11];
    const float* vb     = (const float*)d_in[12];
    const float* wo     = (const float*)d_in[13];
    const float* bo     = (const float*)d_in[14];
    float* out = (float*)d_out;

    float *xn, *qu, *qv, *kx, *vx, *px, *ctx, *sc, *bd;
    cudaGetSymbolAddress((void**)&xn,  g_xn);
    cudaGetSymbolAddress((void**)&qu,  g_qu);
    cudaGetSymbolAddress((void**)&qv,  g_qv);
    cudaGetSymbolAddress((void**)&kx,  g_k);
    cudaGetSymbolAddress((void**)&vx,  g_v);
    cudaGetSymbolAddress((void**)&px,  g_p);
    cudaGetSymbolAddress((void**)&ctx, g_ctx);
    cudaGetSymbolAddress((void**)&sc,  g_scores);
    cudaGetSymbolAddress((void**)&bd,  g_bd);

    // 1. LayerNorm
    ln_kernel<<<M, 128>>>(inputs, gamma, beta, xn);

    // 2. Projections
    dim3 gg(8, 128);
    sgemm512<<<gg, 256>>>(xn,  wq,   bq,  u,    nullptr, qu, vb, qv);     // Q+u, Q+v
    sgemm512<<<gg, 256>>>(xn,  wk,   bk,  nullptr, nullptr, kx, nullptr, nullptr);
    sgemm512<<<gg, 256>>>(xn,  wv,   bv,  nullptr, nullptr, vx, nullptr, nullptr);
    sgemm512<<<gg, 256>>>(pos, wpos, nullptr, nullptr, nullptr, px, nullptr, nullptr);

    // 3. Scores
    dim3 sg(16, 16, NB * H);
    score_gemm<<<sg, 256>>>(qu, kx, sc);  // content
    score_gemm<<<sg, 256>>>(qv, px, bd);  // positional (pre-shift)

    // 4. shift + softmax (in place on sc)
    softmax_shift<<<dim3(T, NB * H), 256>>>(sc, bd);

    // 5. attn @ V
    attn_v<<<dim3(16, NB * H), 256>>>(sc, vx, ctx);

    // 6. output projection + bias + residual
    sgemm512<<<gg, 256>>>(ctx, wo, bo, nullptr, inputs, out, nullptr, nullptr);
}

// round 2
// speedup vs baseline: 2.7116x; 2.7116x over previous
#include <cuda_runtime.h>
#include <cstdint>

// Problem constants
constexpr int NB = 8;      // batch
constexpr int T  = 1024;   // sequence
constexpr int D  = 512;    // model dim
constexpr int H  = 8;      // heads
constexpr int HD = 64;     // head dim
constexpr int M  = NB * T; // 8192 rows

// ---------------- scratch (device globals; allocation-free at runtime) -------
__device__ float g_xn[M * D];
__device__ float g_qu[M * D];
__device__ float g_qv[M * D];
__device__ float g_k [M * D];
__device__ float g_v [M * D];
__device__ float g_p [M * D];
__device__ float g_ctx[M * D];
__device__ float g_scores[(size_t)NB * H * T * T];
__device__ float g_bd    [(size_t)NB * H * T * T];

// ---------------- tf32 helpers ----------------------------------------------
__device__ __forceinline__ uint32_t f2tf(float f) {
    uint32_t u; asm("cvt.rna.tf32.f32 %0, %1;" : "=r"(u) : "f"(f)); return u;
}
__device__ __forceinline__ void mma8(float* c, const uint32_t* a, const uint32_t* b) {
    asm volatile(
        "mma.sync.aligned.m16n8k8.row.col.f32.tf32.tf32.f32 "
        "{%0,%1,%2,%3}, {%4,%5,%6,%7}, {%8,%9}, {%0,%1,%2,%3};\n"
        : "+f"(c[0]), "+f"(c[1]), "+f"(c[2]), "+f"(c[3])
        : "r"(a[0]), "r"(a[1]), "r"(a[2]), "r"(a[3]), "r"(b[0]), "r"(b[1]));
}

// ---------------- LayerNorm --------------------------------------------------
__global__ void ln_kernel(const float* __restrict__ x,
                          const float* __restrict__ gamma,
                          const float* __restrict__ beta,
                          float* __restrict__ out) {
    int row = blockIdx.x;
    int t = threadIdx.x; // 128 threads
    const float4* xr = reinterpret_cast<const float4*>(x + (size_t)row * D);
    float4 v = xr[t];
    float s = v.x + v.y + v.z + v.w;
    __shared__ float red[4], red2[4];
    #pragma unroll
    for (int o = 16; o > 0; o >>= 1) s += __shfl_xor_sync(0xffffffffu, s, o);
    if ((t & 31) == 0) red[t >> 5] = s;
    __syncthreads();
    float mu = (red[0] + red[1] + red[2] + red[3]) * (1.0f / D);
    float dx = v.x - mu, dy = v.y - mu, dz = v.z - mu, dw = v.w - mu;
    float ss = dx * dx + dy * dy + dz * dz + dw * dw;
    #pragma unroll
    for (int o = 16; o > 0; o >>= 1) ss += __shfl_xor_sync(0xffffffffu, ss, o);
    if ((t & 31) == 0) red2[t >> 5] = ss;
    __syncthreads();
    float var = (red2[0] + red2[1] + red2[2] + red2[3]) * (1.0f / D);
    float rstd = rsqrtf(var + 1e-3f);
    const float4* g4 = reinterpret_cast<const float4*>(gamma);
    const float4* b4 = reinterpret_cast<const float4*>(beta);
    float4 g = g4[t], b = b4[t];
    float4 o4;
    o4.x = dx * rstd * g.x + b.x;
    o4.y = dy * rstd * g.y + b.y;
    o4.z = dz * rstd * g.z + b.z;
    o4.w = dw * rstd * g.w + b.w;
    reinterpret_cast<float4*>(out + (size_t)row * D)[t] = o4;
}

// ---------------- tf32 SGEMM: C[M,512] = A[M,512] @ W[512,512] ---------------
// BM=128, BN=128, BK=32, 256 thr, 8 warps (4 in M x 2 in N), warp tile 32x64.
__global__ void __launch_bounds__(256) sgemm512_tf32(
    const float* __restrict__ A, const float* __restrict__ W,
    const float* __restrict__ bias, const float* __restrict__ biasU,
    const float* __restrict__ resid, float* __restrict__ out1,
    const float* __restrict__ biasV, float* __restrict__ out2) {
    __shared__ uint32_t As[128][36];   // pitch 36 (==4 mod 32): A-frag pattern CF
    __shared__ uint32_t Bs[32][136];   // pitch 136 (==8 mod 32): B-frag pattern CF
    int t = threadIdx.x;
    int bm = blockIdx.y * 128, bn = blockIdx.x * 128;
    int wid = t >> 5, lane = t & 31;
    int wm = wid & 3, wn = wid >> 2;
    int g = lane >> 2, q4 = lane & 3;

    float acc[2][8][4];
    #pragma unroll
    for (int i = 0; i < 2; i++)
        #pragma unroll
        for (int j = 0; j < 8; j++)
            #pragma unroll
            for (int k = 0; k < 4; k++) acc[i][j][k] = 0.f;

    int arow = t >> 3, ac4 = (t & 7) * 4;   // A tile: 128 rows x 8 f4
    int brow = t >> 5, bc4 = (t & 31) * 4;  // B tile: 32 rows x 32 f4

    float4 av[4], bv[4];
    #pragma unroll
    for (int p = 0; p < 4; p++)
        av[p] = *reinterpret_cast<const float4*>(A + (size_t)(bm + arow + p * 32) * D + ac4);
    #pragma unroll
    for (int p = 0; p < 4; p++)
        bv[p] = *reinterpret_cast<const float4*>(W + (size_t)(brow + p * 8) * D + bn + bc4);

    for (int k0 = 0; k0 < D; k0 += 32) {
        __syncthreads();
        #pragma unroll
        for (int p = 0; p < 4; p++) {
            int r = arow + p * 32;
            As[r][ac4 + 0] = f2tf(av[p].x); As[r][ac4 + 1] = f2tf(av[p].y);
            As[r][ac4 + 2] = f2tf(av[p].z); As[r][ac4 + 3] = f2tf(av[p].w);
        }
        #pragma unroll
        for (int p = 0; p < 4; p++) {
            int r = brow + p * 8;
            Bs[r][bc4 + 0] = f2tf(bv[p].x); Bs[r][bc4 + 1] = f2tf(bv[p].y);
            Bs[r][bc4 + 2] = f2tf(bv[p].z); Bs[r][bc4 + 3] = f2tf(bv[p].w);
        }
        __syncthreads();
        if (k0 + 32 < D) {
            #pragma unroll
            for (int p = 0; p < 4; p++)
                av[p] = *reinterpret_cast<const float4*>(A + (size_t)(bm + arow + p * 32) * D + k0 + 32 + ac4);
            #pragma unroll
            for (int p = 0; p < 4; p++)
                bv[p] = *reinterpret_cast<const float4*>(W + (size_t)(k0 + 32 + brow + p * 8) * D + bn + bc4);
        }
        #pragma unroll
        for (int kc = 0; kc < 4; kc++) {
            int kb = kc * 8;
            uint32_t af[2][4];
            #pragma unroll
            for (int mt = 0; mt < 2; mt++) {
                int r = wm * 32 + mt * 16 + g;
                af[mt][0] = As[r][kb + q4];      af[mt][1] = As[r + 8][kb + q4];
                af[mt][2] = As[r][kb + q4 + 4];  af[mt][3] = As[r + 8][kb + q4 + 4];
            }
            #pragma unroll
            for (int nt = 0; nt < 8; nt++) {
                int c = wn * 64 + nt * 8 + g;
                uint32_t bf[2];
                bf[0] = Bs[kb + q4][c]; bf[1] = Bs[kb + q4 + 4][c];
                mma8(acc[0][nt], af[0], bf);
                mma8(acc[1][nt], af[1], bf);
            }
        }
    }

    #pragma unroll
    for (int mt = 0; mt < 2; mt++) {
        int r0 = bm + wm * 32 + mt * 16 + g;
        #pragma unroll
        for (int nt = 0; nt < 8; nt++) {
            int c0 = bn + wn * 64 + nt * 8 + q4 * 2;
            #pragma unroll
            for (int rr = 0; rr < 2; rr++) {
                int r = r0 + rr * 8;
                float b0 = acc[mt][nt][rr * 2 + 0];
                float b1 = acc[mt][nt][rr * 2 + 1];
                if (bias) { b0 += bias[c0]; b1 += bias[c0 + 1]; }
                float v0 = b0, v1 = b1;
                if (biasU) { v0 += biasU[c0]; v1 += biasU[c0 + 1]; }
                if (resid) {
                    float2 rv = *reinterpret_cast<const float2*>(resid + (size_t)r * D + c0);
                    v0 += rv.x; v1 += rv.y;
                }
                *reinterpret_cast<float2*>(out1 + (size_t)r * D + c0) = make_float2(v0, v1);
                if (out2) {
                    float w0 = b0 + biasV[c0], w1 = b1 + biasV[c0 + 1];
                    *reinterpret_cast<float2*>(out2 + (size_t)r * D + c0) = make_float2(w0, w1);
                }
            }
        }
    }
}

// ---------------- tf32 score GEMM: S[bh,i,j] = sum_c Q[i,c]*K[j,c] -----------
// Persistent over j: Q tile (128x64) resident, K tile (128x64) streamed.
// 8 warps (4 in M x 2 in N), warp tile 32x64, BK=64 (8 k-chunks).
__global__ void __launch_bounds__(256) score_tf32(
    const float* __restrict__ Qx, const float* __restrict__ Kx, float* __restrict__ S) {
    extern __shared__ uint32_t sm4[];
    uint32_t (*Qs)[68] = reinterpret_cast<uint32_t(*)[68]>(sm4);
    uint32_t (*Ks)[68] = reinterpret_cast<uint32_t(*)[68]>(sm4 + 128 * 68);
    int bh = blockIdx.y;
    int b = bh >> 3, h = bh & 7;
    int i0 = blockIdx.x * 128;
    const float* Qb = Qx + (size_t)b * T * D + h * HD;
    const float* Kb = Kx + (size_t)b * T * D + h * HD;
    int t = threadIdx.x, wid = t >> 5, lane = t & 31;
    int wm = wid & 3, wn = wid >> 2;
    int g = lane >> 2, q4 = lane & 3;
    int lrow = t >> 4, lc4 = (t & 15) * 4;   // 16 rows/pass x 16 f4

    #pragma unroll
    for (int p = 0; p < 8; p++) {
        int r = lrow + p * 16;
        float4 v = *reinterpret_cast<const float4*>(Qb + (size_t)(i0 + r) * D + lc4);
        Qs[r][lc4 + 0] = f2tf(v.x); Qs[r][lc4 + 1] = f2tf(v.y);
        Qs[r][lc4 + 2] = f2tf(v.z); Qs[r][lc4 + 3] = f2tf(v.w);
    }

    for (int j0 = 0; j0 < T; j0 += 128) {
        __syncthreads();
        #pragma unroll
        for (int p = 0; p < 8; p++) {
            int r = lrow + p * 16;
            float4 v = *reinterpret_cast<const float4*>(Kb + (size_t)(j0 + r) * D + lc4);
            Ks[r][lc4 + 0] = f2tf(v.x); Ks[r][lc4 + 1] = f2tf(v.y);
            Ks[r][lc4 + 2] = f2tf(v.z); Ks[r][lc4 + 3] = f2tf(v.w);
        }
        __syncthreads();

        float acc[2][8][4];
        #pragma unroll
        for (int i = 0; i < 2; i++)
            #pragma unroll
            for (int j = 0; j < 8; j++)
                #pragma unroll
                for (int k = 0; k < 4; k++) acc[i][j][k] = 0.f;

        #pragma unroll
        for (int kc = 0; kc < 8; kc++) {
            int kb = kc * 8;
            uint32_t af[2][4];
            #pragma unroll
            for (int mt = 0; mt < 2; mt++) {
                int r = wm * 32 + mt * 16 + g;
                af[mt][0] = Qs[r][kb + q4];      af[mt][1] = Qs[r + 8][kb + q4];
                af[mt][2] = Qs[r][kb + q4 + 4];  af[mt][3] = Qs[r + 8][kb + q4 + 4];
            }
            #pragma unroll
            for (int nt = 0; nt < 8; nt++) {
                int c = wn * 64 + nt * 8 + g;
                uint32_t bf[2];
                bf[0] = Ks[c][kb + q4]; bf[1] = Ks[c][kb + q4 + 4];
                mma8(acc[0][nt], af[0], bf);
                mma8(acc[1][nt], af[1], bf);
            }
        }

        #pragma unroll
        for (int mt = 0; mt < 2; mt++) {
            int r0 = i0 + wm * 32 + mt * 16 + g;
            #pragma unroll
            for (int nt = 0; nt < 8; nt++) {
                int c0 = j0 + wn * 64 + nt * 8 + q4 * 2;
                size_t base = ((size_t)bh * T + r0) * T + c0;
                *reinterpret_cast<float2*>(S + base) =
                    make_float2(acc[mt][nt][0], acc[mt][nt][1]);
                *reinterpret_cast<float2*>(S + base + (size_t)8 * T) =
                    make_float2(acc[mt][nt][2], acc[mt][nt][3]);
            }
        }
    }
}

// ---------------- shift + softmax (row-wise, in place on S) ------------------
__global__ void softmax_shift(float* __restrict__ S, const float* __restrict__ BD) {
    int i = blockIdx.x;
    int bh = blockIdx.y;
    size_t rowOff = ((size_t)bh * T + i) * T;
    float* srow = S + rowOff;
    const float* bdi  = BD + rowOff;
    const float* bdi1 = bdi + T;
    int t = threadIdx.x; // 256
    float vals[4];
    float mx = -3.4e38f;
    #pragma unroll
    for (int q = 0; q < 4; q++) {
        int j = q * 256 + t;
        float sh;
        if (j <= i)           sh = bdi[T - 1 - i + j];
        else if (j == i + 1)  sh = 0.f;
        else                  sh = bdi1[j - i - 2];
        float val = (srow[j] + sh) * 0.125f;
        vals[q] = val;
        mx = fmaxf(mx, val);
    }
    __shared__ float red[8], red2[8];
    #pragma unroll
    for (int o = 16; o > 0; o >>= 1) mx = fmaxf(mx, __shfl_xor_sync(0xffffffffu, mx, o));
    if ((t & 31) == 0) red[t >> 5] = mx;
    __syncthreads();
    mx = red[0];
    #pragma unroll
    for (int w = 1; w < 8; w++) mx = fmaxf(mx, red[w]);
    float sum = 0.f;
    #pragma unroll
    for (int q = 0; q < 4; q++) {
        vals[q] = expf(vals[q] - mx);
        sum += vals[q];
    }
    #pragma unroll
    for (int o = 16; o > 0; o >>= 1) sum += __shfl_xor_sync(0xffffffffu, sum, o);
    if ((t & 31) == 0) red2[t >> 5] = sum;
    __syncthreads();
    sum = red2[0] + red2[1] + red2[2] + red2[3] + red2[4] + red2[5] + red2[6] + red2[7];
    float inv = 1.0f / sum;
    #pragma unroll
    for (int q = 0; q < 4; q++) {
        int j = q * 256 + t;
        srow[j] = vals[q] * inv;
    }
}

// ---------------- tf32 attn @ V: ctx[i,f] = sum_j S[i,j] V[j,f] --------------
// BM=128, BN=64, BK=32, 8 warps (4 in M x 2 in N), warp tile 32x32.
__global__ void __launch_bounds__(256) attnv_tf32(
    const float* __restrict__ S, const float* __restrict__ V, float* __restrict__ ctx) {
    __shared__ uint32_t As[128][36];  // S tile, [m][k], pitch 36
    __shared__ uint32_t Vs[32][72];   // V tile, [k=j][n=f], pitch 72 (==8 mod 32)
    int bh = blockIdx.y;
    int b = bh >> 3, h = bh & 7;
    int i0 = blockIdx.x * 128;
    const float* Sb = S + ((size_t)bh * T + i0) * T;
    const float* Vb = V + (size_t)b * T * D + h * HD;
    int t = threadIdx.x, wid = t >> 5, lane = t & 31;
    int wm = wid & 3, wn = wid >> 2;
    int g = lane >> 2, q4 = lane & 3;

    int srow = t >> 3, sc4 = (t & 7) * 4;    // S tile: 32 rows/pass x 8 f4, 4 passes
    int vrow = t >> 4, vc4 = (t & 15) * 4;   // V tile: 16 rows/pass x 16 f4, 2 passes

    float acc[2][4][4];
    #pragma unroll
    for (int i = 0; i < 2; i++)
        #pragma unroll
        for (int j = 0; j < 4; j++)
            #pragma unroll
            for (int k = 0; k < 4; k++) acc[i][j][k] = 0.f;

    float4 sv[4], vv[2];
    #pragma unroll
    for (int p = 0; p < 4; p++)
        sv[p] = *reinterpret_cast<const float4*>(Sb + (size_t)(srow + p * 32) * T + sc4);
    #pragma unroll
    for (int p = 0; p < 2; p++)
        vv[p] = *reinterpret_cast<const float4*>(Vb + (size_t)(vrow + p * 16) * D + vc4);

    for (int k0 = 0; k0 < T; k0 += 32) {
        __syncthreads();
        #pragma unroll
        for (int p = 0; p < 4; p++) {
            int r = srow + p * 32;
            As[r][sc4 + 0] = f2tf(sv[p].x); As[r][sc4 + 1] = f2tf(sv[p].y);
            As[r][sc4 + 2] = f2tf(sv[p].z); As[r][sc4 + 3] = f2tf(sv[p].w);
        }
        #pragma unroll
        for (int p = 0; p < 2; p++) {
            int r = vrow + p * 16;
            Vs[r][vc4 + 0] = f2tf(vv[p].x); Vs[r][vc4 + 1] = f2tf(vv[p].y);
            Vs[r][vc4 + 2] = f2tf(vv[p].z); Vs[r][vc4 + 3] = f2tf(vv[p].w);
        }
        __syncthreads();
        if (k0 + 32 < T) {
            #pragma unroll
            for (int p = 0; p < 4; p++)
                sv[p] = *reinterpret_cast<const float4*>(Sb + (size_t)(srow + p * 32) * T + k0 + 32 + sc4);
            #pragma unroll
            for (int p = 0; p < 2; p++)
                vv[p] = *reinterpret_cast<const float4*>(Vb + (size_t)(k0 + 32 + vrow + p * 16) * D + vc4);
        }
        #pragma unroll
        for (int kc = 0; kc < 4; kc++) {
            int kb = kc * 8;
            uint32_t af[2][4];
            #pragma unroll
            for (int mt = 0; mt < 2; mt++) {
                int r = wm * 32 + mt * 16 + g;
                af[mt][0] = As[r][kb + q4];      af[mt][1] = As[r + 8][kb + q4];
                af[mt][2] = As[r][kb + q4 + 4];  af[mt][3] = As[r + 8][kb + q4 + 4];
            }
            #pragma unroll
            for (int nt = 0; nt < 4; nt++) {
                int c = wn * 32 + nt * 8 + g;
                uint32_t bf[2];
                bf[0] = Vs[kb + q4][c]; bf[1] = Vs[kb + q4 + 4][c];
                mma8(acc[0][nt], af[0], bf);
                mma8(acc[1][nt], af[1], bf);
            }
        }
    }

    float* Cg = ctx + ((size_t)(b * T + i0)) * D + h * HD;
    #pragma unroll
    for (int mt = 0; mt < 2; mt++) {
        int r0 = wm * 32 + mt * 16 + g;
        #pragma unroll
        for (int nt = 0; nt < 4; nt++) {
            int c0 = wn * 32 + nt * 8 + q4 * 2;
            *reinterpret_cast<float2*>(Cg + (size_t)r0 * D + c0) =
                make_float2(acc[mt][nt][0], acc[mt][nt][1]);
            *reinterpret_cast<float2*>(Cg + (size_t)(r0 + 8) * D + c0) =
                make_float2(acc[mt][nt][2], acc[mt][nt][3]);
        }
    }
}

// ---------------- launch -----------------------------------------------------
extern "C" void kernel_launch(void* const* d_in, const int* in_sizes, int n_in,
                              void* d_out, int out_size) {
    const float* inputs = (const float*)d_in[0];
    const float* pos    = (const float*)d_in[1];
    const float* gamma  = (const float*)d_in[2];
    const float* beta   = (const float*)d_in[3];
    const float* wq     = (const float*)d_in[4];
    const float* bq     = (const float*)d_in[5];
    const float* wk     = (const float*)d_in[6];
    const float* bk     = (const float*)d_in[7];
    const float* wv     = (const float*)d_in[8];
    const float* bv     = (const float*)d_in[9];
    const float* wpos   = (const float*)d_in[10];
    const float* u      = (const float*)d_in[11];
    const float* vb     = (const float*)d_in[12];
    const float* wo     = (const float*)d_in[13];
    const float* bo     = (const float*)d_in[14];
    float* out = (float*)d_out;

    float *xn, *qu, *qv, *kx, *vx, *px, *ctx, *sc, *bd;
    cudaGetSymbolAddress((void**)&xn,  g_xn);
    cudaGetSymbolAddress((void**)&qu,  g_qu);
    cudaGetSymbolAddress((void**)&qv,  g_qv);
    cudaGetSymbolAddress((void**)&kx,  g_k);
    cudaGetSymbolAddress((void**)&vx,  g_v);
    cudaGetSymbolAddress((void**)&px,  g_p);
    cudaGetSymbolAddress((void**)&ctx, g_ctx);
    cudaGetSymbolAddress((void**)&sc,  g_scores);
    cudaGetSymbolAddress((void**)&bd,  g_bd);

    const int SCORE_SMEM = 2 * 128 * 68 * 4; // 69632 B
    cudaFuncSetAttribute(score_tf32, cudaFuncAttributeMaxDynamicSharedMemorySize, SCORE_SMEM);

    // 1. LayerNorm
    ln_kernel<<<M, 128>>>(inputs, gamma, beta, xn);

    // 2. Projections (tf32 MMA)
    dim3 gg(4, 64); // N/128 x M/128
    sgemm512_tf32<<<gg, 256>>>(xn,  wq,   bq,      u,       nullptr, qu, vb, qv);
    sgemm512_tf32<<<gg, 256>>>(xn,  wk,   bk,      nullptr, nullptr, kx, nullptr, nullptr);
    sgemm512_tf32<<<gg, 256>>>(xn,  wv,   bv,      nullptr, nullptr, vx, nullptr, nullptr);
    sgemm512_tf32<<<gg, 256>>>(pos, wpos, nullptr, nullptr, nullptr, px, nullptr, nullptr);

    // 3. Scores (tf32 MMA, persistent over j)
    dim3 sg(8, NB * H); // i-tiles x bh
    score_tf32<<<sg, 256, SCORE_SMEM>>>(qu, kx, sc);  // content
    score_tf32<<<sg, 256, SCORE_SMEM>>>(qv, px, bd);  // positional (pre-shift)

    // 4. shift + softmax (in place on sc)
    softmax_shift<<<dim3(T, NB * H), 256>>>(sc, bd);

    // 5. attn @ V (tf32 MMA)
    attnv_tf32<<<dim3(8, NB * H), 256>>>(sc, vx, ctx);

    // 6. output projection + bias + residual
    sgemm512_tf32<<<gg, 256>>>(ctx, wo, bo, nullptr, inputs, out, nullptr, nullptr);
}